// round 12
// baseline (speedup 1.0000x reference)
#include <cuda_runtime.h>
#include <cuda_bf16.h>
#include <cstdint>

// ---------------------------------------------------------------------------
// HeteroGraphSAGE forward on GB300 — round 6:
//  - mma.sync bf16 split-3 GEMM with cp.async (LDGSTS) double-buffered fp32
//    staging; smem->smem bf16 split conversion; 2 CTAs/SM.
//  - final layer scatters directly into d_out (no agg2 buffers/memsets).
// ---------------------------------------------------------------------------

#define NU   100000
#define NI   200000
#define NE   600000
#define DIN  128
#define DHID 256
#define DOUT 128

// scratch layout (floats)
#define OFF_XI      0LL
#define OFF_AGG_I   25600000LL
#define OFF_AGG_U   51200000LL
#define OFF_H_I     64000000LL
#define OFF_H_U     115200000LL
#define OFF_Y_U2    140800000LL
#define OFF_Y_I2    153600000LL
#define SCRATCH_SZ  179200000LL

__device__ float g_scratch[SCRATCH_SZ];

// ---------------------------------------------------------------------------
// helpers
// ---------------------------------------------------------------------------
__device__ __forceinline__ uint32_t smem_u32(const void* p) {
    uint32_t a;
    asm("{ .reg .u64 t; cvta.to.shared.u64 t, %1; cvt.u32.u64 %0, t; }"
        : "=r"(a) : "l"(p));
    return a;
}

__device__ __forceinline__ void ldsm4(uint32_t* r, uint32_t addr) {
    asm volatile("ldmatrix.sync.aligned.m8n8.x4.shared.b16 {%0,%1,%2,%3}, [%4];"
                 : "=r"(r[0]), "=r"(r[1]), "=r"(r[2]), "=r"(r[3])
                 : "r"(addr));
}

__device__ __forceinline__ void mma_bf16(float* c, const uint32_t* a,
                                         const uint32_t* b) {
    asm volatile(
        "mma.sync.aligned.m16n8k16.row.col.f32.bf16.bf16.f32 "
        "{%0,%1,%2,%3}, {%4,%5,%6,%7}, {%8,%9}, {%0,%1,%2,%3};"
        : "+f"(c[0]), "+f"(c[1]), "+f"(c[2]), "+f"(c[3])
        : "r"(a[0]), "r"(a[1]), "r"(a[2]), "r"(a[3]),
          "r"(b[0]), "r"(b[1]));
}

__device__ __forceinline__ void cpasync16(uint32_t dst, const void* src,
                                          int src_size) {
    asm volatile("cp.async.ca.shared.global [%0], [%1], 16, %2;"
                 :: "r"(dst), "l"(src), "r"(src_size) : "memory");
}
__device__ __forceinline__ void cp_commit() {
    asm volatile("cp.async.commit_group;" ::: "memory");
}
__device__ __forceinline__ void cp_wait1() {
    asm volatile("cp.async.wait_group 1;" ::: "memory");
}

// split fp32x4 -> bf16 hi x4 (8B) + lo x4 (8B)
__device__ __forceinline__ void split_store(__nv_bfloat16* hi_p,
                                            __nv_bfloat16* lo_p, float4 v) {
    __nv_bfloat162 h0 = __floats2bfloat162_rn(v.x, v.y);
    __nv_bfloat162 h1 = __floats2bfloat162_rn(v.z, v.w);
    float2 f0 = __bfloat1622float2(h0);
    float2 f1 = __bfloat1622float2(h1);
    __nv_bfloat162 l0 = __floats2bfloat162_rn(v.x - f0.x, v.y - f0.y);
    __nv_bfloat162 l1 = __floats2bfloat162_rn(v.z - f1.x, v.w - f1.y);
    uint2 hu, lu;
    hu.x = *(uint32_t*)&h0; hu.y = *(uint32_t*)&h1;
    lu.x = *(uint32_t*)&l0; lu.y = *(uint32_t*)&l1;
    *(uint2*)hi_p = hu;
    *(uint2*)lo_p = lu;
}

// ---------------------------------------------------------------------------
// cp.async-pipelined tensor-core fused GEMM (mma.sync bf16, split-3):
//   C[M,N] = A1[M,K]@W1[N,K]^T (+ A2@W2^T) (+ bias) (+ addend) [relu]
// CTA tile 128x128, BK=32 fp32 per chunk, 8 warps 4(m)x2(n), warp 32x64.
// fp32 stage double-buffered via cp.async (depth 2); bf16 tiles single buf.
// ---------------------------------------------------------------------------
#define LDT 40
#define TILE_ELEMS (128 * LDT)              // bf16 per tile
#define STG_ELEMS  (128 * 32)               // fp32 per stage matrix
// smem: stA[2][4096]f, stB[2][4096]f, Ah/Al/Bh/Bl[5120]bf16  = 104 KB
#define SMEM_TOTAL_B (2 * STG_ELEMS * 4 * 2 + 4 * TILE_ELEMS * 2)

// issue cp.async loads for one 128x32 chunk of A and B
__device__ __forceinline__ void issue_chunk(
    const float* __restrict__ A, const float* __restrict__ W,
    int bm, int bn, int M, int K, int k0, int tid,
    uint32_t stA_u, uint32_t stB_u)
{
    const int m0 = tid >> 3;
    const int k4 = (tid & 7) * 4;
#pragma unroll
    for (int i = 0; i < 4; i++) {
        int m  = m0 + i * 32;
        int gr = bm + m;
        int ok = (gr < M);
        const float* pa = A + (size_t)(ok ? gr : 0) * K + k0 + k4;
        cpasync16(stA_u + (uint32_t)(m * 32 + k4) * 4, pa, ok ? 16 : 0);
        const float* pb = W + (size_t)(bn + m) * K + k0 + k4;
        cpasync16(stB_u + (uint32_t)(m * 32 + k4) * 4, pb, 16);
    }
}

__global__ void __launch_bounds__(256) gemm_mma_kernel(
    const float* __restrict__ A1, const float* __restrict__ W1,
    const float* __restrict__ bias,
    const float* __restrict__ A2, const float* __restrict__ W2,
    const float* __restrict__ addend,
    float* __restrict__ C, int M, int N, int K, int do_relu)
{
    extern __shared__ __align__(16) char smraw[];
    float* stA = (float*)smraw;                         // [2][4096]
    float* stB = stA + 2 * STG_ELEMS;                   // [2][4096]
    __nv_bfloat16* Ah = (__nv_bfloat16*)(stB + 2 * STG_ELEMS);
    __nv_bfloat16* Al = Ah + TILE_ELEMS;
    __nv_bfloat16* Bh = Ah + 2 * TILE_ELEMS;
    __nv_bfloat16* Bl = Ah + 3 * TILE_ELEMS;

    const uint32_t stA_u = smem_u32(stA);
    const uint32_t stB_u = smem_u32(stB);
    const uint32_t sAh   = smem_u32(Ah);
    const uint32_t sAl   = smem_u32(Al);
    const uint32_t sBh   = smem_u32(Bh);
    const uint32_t sBl   = smem_u32(Bl);

    const int tid    = threadIdx.x;
    const int lane   = tid & 31;
    const int wid    = tid >> 5;
    const int warp_m = wid & 3;
    const int warp_n = wid >> 2;
    const int bm     = blockIdx.x * 128;
    const int bn     = blockIdx.y * 128;

    float acc[2][8][4];
#pragma unroll
    for (int f = 0; f < 2; f++)
#pragma unroll
        for (int j = 0; j < 8; j++)
#pragma unroll
            for (int q = 0; q < 4; q++) acc[f][j][q] = 0.0f;

    const int a_r = lane & 15;
    const int a_c = (lane >> 4) * 8;
    const int b_r = (lane & 7) + ((lane >> 4) & 1) * 8;
    const int b_c = ((lane >> 3) & 1) * 8;

    const int cpp   = K / 32;
    const int npass = (A2 != nullptr) ? 2 : 1;
    const int nch   = npass * cpp;

    const int cv_m  = tid >> 3;          // conversion row base
    const int cv_k4 = (tid & 7) * 4;

    // prologue: chunks 0 and 1 in flight
    issue_chunk(A1, W1, bm, bn, M, K, 0, tid,
                stA_u, stB_u);
    cp_commit();
    {
        int c1 = 1;
        int p  = c1 / cpp;
        int k0 = (c1 - p * cpp) * 32;
        if (c1 < nch)
            issue_chunk(p ? A2 : A1, p ? W2 : W1, bm, bn, M, K, k0, tid,
                        stA_u + STG_ELEMS * 4 * (c1 & 1),
                        stB_u + STG_ELEMS * 4 * (c1 & 1));
        cp_commit();
    }

    for (int c = 0; c < nch; c++) {
        cp_wait1();                      // group for chunk c complete
        __syncthreads();

        // convert fp32 stage -> bf16 hi/lo tiles
        const float* sA = stA + (c & 1) * STG_ELEMS;
        const float* sB = stB + (c & 1) * STG_ELEMS;
#pragma unroll
        for (int i = 0; i < 4; i++) {
            int m = cv_m + i * 32;
            float4 va = *(const float4*)(sA + m * 32 + cv_k4);
            float4 vb = *(const float4*)(sB + m * 32 + cv_k4);
            split_store(&Ah[m * LDT + cv_k4], &Al[m * LDT + cv_k4], va);
            split_store(&Bh[m * LDT + cv_k4], &Bl[m * LDT + cv_k4], vb);
        }
        __syncthreads();

        // issue chunk c+2 (uniform commit keeps group counts aligned)
        {
            int cn = c + 2;
            if (cn < nch) {
                int p  = cn / cpp;
                int k0 = (cn - p * cpp) * 32;
                issue_chunk(p ? A2 : A1, p ? W2 : W1, bm, bn, M, K, k0, tid,
                            stA_u + STG_ELEMS * 4 * (cn & 1),
                            stB_u + STG_ELEMS * 4 * (cn & 1));
            }
            cp_commit();
        }

        // MMA over the bf16 tiles
#pragma unroll
        for (int ks = 0; ks < 32; ks += 16) {
            uint32_t ah[8], bx[16];

#pragma unroll
            for (int f = 0; f < 2; f++) {
                int row = warp_m * 32 + f * 16 + a_r;
                ldsm4(&ah[4 * f], sAh + (uint32_t)(row * LDT + ks + a_c) * 2);
            }
#pragma unroll
            for (int g = 0; g < 4; g++) {
                int row = warp_n * 64 + g * 16 + b_r;
                ldsm4(&bx[4 * g], sBh + (uint32_t)(row * LDT + ks + b_c) * 2);
            }
            // hh
#pragma unroll
            for (int f = 0; f < 2; f++)
#pragma unroll
                for (int j = 0; j < 8; j++)
                    mma_bf16(acc[f][j], &ah[4 * f], &bx[2 * j]);

            // lh: al x bh
            {
                uint32_t al[8];
#pragma unroll
                for (int f = 0; f < 2; f++) {
                    int row = warp_m * 32 + f * 16 + a_r;
                    ldsm4(&al[4 * f],
                          sAl + (uint32_t)(row * LDT + ks + a_c) * 2);
                }
#pragma unroll
                for (int f = 0; f < 2; f++)
#pragma unroll
                    for (int j = 0; j < 8; j++)
                        mma_bf16(acc[f][j], &al[4 * f], &bx[2 * j]);
            }
            // hl: ah x bl (overwrite bx)
#pragma unroll
            for (int g = 0; g < 4; g++) {
                int row = warp_n * 64 + g * 16 + b_r;
                ldsm4(&bx[4 * g], sBl + (uint32_t)(row * LDT + ks + b_c) * 2);
            }
#pragma unroll
            for (int f = 0; f < 2; f++)
#pragma unroll
                for (int j = 0; j < 8; j++)
                    mma_bf16(acc[f][j], &ah[4 * f], &bx[2 * j]);
        }
    }

    // ---- epilogue ----
#pragma unroll
    for (int f = 0; f < 2; f++) {
        int r0 = warp_m * 32 + f * 16 + (lane >> 2);
#pragma unroll
        for (int half = 0; half < 2; half++) {
            int gr = bm + r0 + half * 8;
            if (gr >= M) continue;
            float* crow = C + (size_t)gr * N;
            const float* arow = addend ? addend + (size_t)gr * N : nullptr;
#pragma unroll
            for (int j = 0; j < 8; j++) {
                int col = bn + warp_n * 64 + j * 8 + (lane & 3) * 2;
                float2 v;
                v.x = acc[f][j][half * 2 + 0];
                v.y = acc[f][j][half * 2 + 1];
                if (bias) {
                    float2 b = *(const float2*)(bias + col);
                    v.x += b.x; v.y += b.y;
                }
                if (arow) {
                    float2 a = *(const float2*)(arow + col);
                    v.x += a.x; v.y += a.y;
                }
                if (do_relu) {
                    v.x = fmaxf(v.x, 0.f);
                    v.y = fmaxf(v.y, 0.f);
                }
                *(float2*)(crow + col) = v;
            }
        }
    }
}

// ---------------------------------------------------------------------------
// Edge scatter-add, F=128:  agg[sidx[e]] += x[gidx[e]]  (red.global.add.v4)
// ---------------------------------------------------------------------------
__global__ void __launch_bounds__(256) scatter_add128_kernel(
    const float* __restrict__ x,
    const int* __restrict__ gidx,
    const int* __restrict__ sidx,
    float* __restrict__ agg, int E)
{
    long long idx = (long long)blockIdx.x * blockDim.x + threadIdx.x;
    if (idx >= (long long)E * 32) return;
    int e = (int)(idx >> 5);
    int c = (int)(idx & 31) * 4;

    int g = __ldg(gidx + e);
    int s = __ldg(sidx + e);
    float4 v = *(const float4*)(x + (size_t)g * 128 + c);
    float* p = agg + (size_t)s * 128 + c;
    asm volatile("red.global.add.v4.f32 [%0], {%1, %2, %3, %4};"
                 :: "l"(p), "f"(v.x), "f"(v.y), "f"(v.z), "f"(v.w)
                 : "memory");
}

// ---------------------------------------------------------------------------

extern "C" void kernel_launch(void* const* d_in, const int* in_sizes, int n_in,
                              void* d_out, int out_size)
{
    const float* x_user       = (const float*)d_in[0];
    const float* x_issue      = (const float*)d_in[1];
    const float* W_mlp        = (const float*)d_in[2];
    const float* b_mlp        = (const float*)d_in[3];
    const float* c1_ui_rel_W  = (const float*)d_in[4];
    const float* c1_ui_rel_b  = (const float*)d_in[5];
    const float* c1_ui_root_W = (const float*)d_in[6];
    const float* c1_iu_rel_W  = (const float*)d_in[7];
    const float* c1_iu_rel_b  = (const float*)d_in[8];
    const float* c1_iu_root_W = (const float*)d_in[9];
    const float* c2_ui_rel_W  = (const float*)d_in[10];
    const float* c2_ui_rel_b  = (const float*)d_in[11];
    const float* c2_ui_root_W = (const float*)d_in[12];
    const float* c2_iu_rel_W  = (const float*)d_in[13];
    const float* c2_iu_rel_b  = (const float*)d_in[14];
    const float* c2_iu_root_W = (const float*)d_in[15];
    const int*   src          = (const int*)d_in[16];
    const int*   dst          = (const int*)d_in[17];

    float* out       = (float*)d_out;
    float* out_issue = out;
    float* out_user  = out + (size_t)NI * DOUT;

    float* S = nullptr;
    cudaGetSymbolAddress((void**)&S, g_scratch);
    float* xi    = S + OFF_XI;
    float* agg_i = S + OFF_AGG_I;
    float* agg_u = S + OFF_AGG_U;
    float* h_i   = S + OFF_H_I;
    float* h_u   = S + OFF_H_U;
    float* y_u2  = S + OFF_Y_U2;
    float* y_i2  = S + OFF_Y_I2;

    cudaFuncSetAttribute(gemm_mma_kernel,
                         cudaFuncAttributeMaxDynamicSharedMemorySize,
                         SMEM_TOTAL_B);

    // zero conv1 aggregation buffers (contiguous: agg_i then agg_u)
    cudaMemsetAsync(agg_i, 0, ((size_t)NI + NU) * DIN * sizeof(float), 0);

    dim3 blk(256);
    const int snb = (int)(((long long)NE * 32 + 255) / 256);
    const int gNI = (NI + 127) / 128;
    const int gNU = (NU + 127) / 128;

    // xi = x_issue @ W_mlp^T + b_mlp      (M=NI, N=128, K=128)
    gemm_mma_kernel<<<dim3(gNI, 1), blk, SMEM_TOTAL_B>>>(
        x_issue, W_mlp, b_mlp, nullptr, nullptr, nullptr,
        xi, NI, DIN, DIN, 0);

    // conv1 scatters (F=128)
    scatter_add128_kernel<<<snb, blk>>>(x_user, src, dst, agg_i, NE);
    scatter_add128_kernel<<<snb, blk>>>(xi,     dst, src, agg_u, NE);

    // h_i = relu(agg_i@c1_ui_rel^T + b + xi@c1_ui_root^T)  (N=256, K=128 x2)
    gemm_mma_kernel<<<dim3(gNI, 2), blk, SMEM_TOTAL_B>>>(
        agg_i, c1_ui_rel_W, c1_ui_rel_b, xi, c1_ui_root_W, nullptr,
        h_i, NI, DHID, DIN, 1);
    // h_u = relu(agg_u@c1_iu_rel^T + b + x_user@c1_iu_root^T)
    gemm_mma_kernel<<<dim3(gNU, 2), blk, SMEM_TOTAL_B>>>(
        agg_u, c1_iu_rel_W, c1_iu_rel_b, x_user, c1_iu_root_W, nullptr,
        h_u, NU, DHID, DIN, 1);

    // conv2 rel: transform-before-scatter (N=128, K=256)
    gemm_mma_kernel<<<dim3(gNU, 1), blk, SMEM_TOTAL_B>>>(
        h_u, c2_ui_rel_W, nullptr, nullptr, nullptr, nullptr,
        y_u2, NU, DOUT, DHID, 0);
    gemm_mma_kernel<<<dim3(gNI, 1), blk, SMEM_TOTAL_B>>>(
        h_i, c2_iu_rel_W, nullptr, nullptr, nullptr, nullptr,
        y_i2, NI, DOUT, DHID, 0);

    // conv2 root GEMMs write d_out directly (bias included)
    gemm_mma_kernel<<<dim3(gNI, 1), blk, SMEM_TOTAL_B>>>(
        h_i, c2_ui_root_W, c2_ui_rel_b, nullptr, nullptr, nullptr,
        out_issue, NI, DOUT, DHID, 0);
    gemm_mma_kernel<<<dim3(gNU, 1), blk, SMEM_TOTAL_B>>>(
        h_u, c2_iu_root_W, c2_iu_rel_b, nullptr, nullptr, nullptr,
        out_user, NU, DOUT, DHID, 0);

    // conv2 scatters add edge messages directly into the outputs
    scatter_add128_kernel<<<snb, blk>>>(y_u2, src, dst, out_issue, NE);
    scatter_add128_kernel<<<snb, blk>>>(y_i2, dst, src, out_user, NE);
}

// round 13
// speedup vs baseline: 1.2358x; 1.2358x over previous
#include <cuda_runtime.h>
#include <cuda_bf16.h>
#include <cstdint>

// ---------------------------------------------------------------------------
// HeteroGraphSAGE forward on GB300 — round 7:
//  - GEMM reverted to round-4 variant (2 CTAs/SM, regs==128): fastest measured.
//  - conv2 scatters write directly into d_out (no agg2 buffers/memsets).
//  - two-stream overlap of the two independent dependency chains.
// ---------------------------------------------------------------------------

#define NU   100000
#define NI   200000
#define NE   600000
#define DIN  128
#define DHID 256
#define DOUT 128

// scratch layout (floats)
#define OFF_XI      0LL
#define OFF_AGG_I   25600000LL
#define OFF_AGG_U   51200000LL
#define OFF_H_I     64000000LL
#define OFF_H_U     115200000LL
#define OFF_Y_U2    140800000LL
#define OFF_Y_I2    153600000LL
#define SCRATCH_SZ  179200000LL

__device__ float g_scratch[SCRATCH_SZ];

// ---------------------------------------------------------------------------
// helpers
// ---------------------------------------------------------------------------
__device__ __forceinline__ uint32_t smem_u32(const void* p) {
    uint32_t a;
    asm("{ .reg .u64 t; cvta.to.shared.u64 t, %1; cvt.u32.u64 %0, t; }"
        : "=r"(a) : "l"(p));
    return a;
}

__device__ __forceinline__ void ldsm4(uint32_t* r, uint32_t addr) {
    asm volatile("ldmatrix.sync.aligned.m8n8.x4.shared.b16 {%0,%1,%2,%3}, [%4];"
                 : "=r"(r[0]), "=r"(r[1]), "=r"(r[2]), "=r"(r[3])
                 : "r"(addr));
}

__device__ __forceinline__ void mma_bf16(float* c, const uint32_t* a,
                                         const uint32_t* b) {
    asm volatile(
        "mma.sync.aligned.m16n8k16.row.col.f32.bf16.bf16.f32 "
        "{%0,%1,%2,%3}, {%4,%5,%6,%7}, {%8,%9}, {%0,%1,%2,%3};"
        : "+f"(c[0]), "+f"(c[1]), "+f"(c[2]), "+f"(c[3])
        : "r"(a[0]), "r"(a[1]), "r"(a[2]), "r"(a[3]),
          "r"(b[0]), "r"(b[1]));
}

// split fp32x4 -> bf16 hi x4 (8B) + lo x4 (8B)
__device__ __forceinline__ void split_store(__nv_bfloat16* hi_p,
                                            __nv_bfloat16* lo_p, float4 v) {
    __nv_bfloat162 h0 = __floats2bfloat162_rn(v.x, v.y);
    __nv_bfloat162 h1 = __floats2bfloat162_rn(v.z, v.w);
    float2 f0 = __bfloat1622float2(h0);
    float2 f1 = __bfloat1622float2(h1);
    __nv_bfloat162 l0 = __floats2bfloat162_rn(v.x - f0.x, v.y - f0.y);
    __nv_bfloat162 l1 = __floats2bfloat162_rn(v.z - f1.x, v.w - f1.y);
    uint2 hu, lu;
    hu.x = *(uint32_t*)&h0; hu.y = *(uint32_t*)&h1;
    lu.x = *(uint32_t*)&l0; lu.y = *(uint32_t*)&l1;
    *(uint2*)hi_p = hu;
    *(uint2*)lo_p = lu;
}

// ---------------------------------------------------------------------------
// Tensor-core fused GEMM (mma.sync bf16, split-3) — round-4 variant:
//   C[M,N] = A1[M,K]@W1[N,K]^T (+ A2@W2^T) (+ bias) (+ addend) [relu]
// CTA tile 128x128, BK=32, 8 warps 4(m)x2(n), warp tile 32x64, 2 CTAs/SM.
// ---------------------------------------------------------------------------
#define LDT 40

__global__ void __launch_bounds__(256, 2) gemm_mma_kernel(
    const float* __restrict__ A1, const float* __restrict__ W1,
    const float* __restrict__ bias,
    const float* __restrict__ A2, const float* __restrict__ W2,
    const float* __restrict__ addend,
    float* __restrict__ C, int M, int N, int K, int do_relu)
{
    __shared__ __align__(16) __nv_bfloat16 Ah[128][LDT];
    __shared__ __align__(16) __nv_bfloat16 Al[128][LDT];
    __shared__ __align__(16) __nv_bfloat16 Bh[128][LDT];
    __shared__ __align__(16) __nv_bfloat16 Bl[128][LDT];

    const int tid    = threadIdx.x;
    const int lane   = tid & 31;
    const int wid    = tid >> 5;
    const int warp_m = wid & 3;
    const int warp_n = wid >> 2;
    const int bm     = blockIdx.x * 128;
    const int bn     = blockIdx.y * 128;

    const uint32_t sAh = smem_u32(Ah);
    const uint32_t sAl = smem_u32(Al);
    const uint32_t sBh = smem_u32(Bh);
    const uint32_t sBl = smem_u32(Bl);

    float acc[2][8][4];
#pragma unroll
    for (int f = 0; f < 2; f++)
#pragma unroll
        for (int j = 0; j < 8; j++)
#pragma unroll
            for (int q = 0; q < 4; q++) acc[f][j][q] = 0.0f;

    const int a_r = lane & 15;
    const int a_c = (lane >> 4) * 8;
    const int b_r = (lane & 7) + ((lane >> 4) & 1) * 8;
    const int b_c = ((lane >> 3) & 1) * 8;

    const int npass = (A2 != nullptr) ? 2 : 1;

    for (int pass = 0; pass < npass; pass++) {
        const float* __restrict__ A = pass ? A2 : A1;
        const float* __restrict__ W = pass ? W2 : W1;

        for (int k0 = 0; k0 < K; k0 += 32) {
#pragma unroll
            for (int i = 0; i < 4; i++) {
                int u  = tid + i * 256;
                int m  = u >> 3;
                int k4 = (u & 7) * 4;
                float4 v = make_float4(0.f, 0.f, 0.f, 0.f);
                int gr = bm + m;
                if (gr < M)
                    v = *(const float4*)(A + (size_t)gr * K + k0 + k4);
                split_store(&Ah[m][k4], &Al[m][k4], v);
            }
#pragma unroll
            for (int i = 0; i < 4; i++) {
                int u  = tid + i * 256;
                int n  = u >> 3;
                int k4 = (u & 7) * 4;
                float4 v = *(const float4*)(W + (size_t)(bn + n) * K + k0 + k4);
                split_store(&Bh[n][k4], &Bl[n][k4], v);
            }
            __syncthreads();

#pragma unroll
            for (int ks = 0; ks < 32; ks += 16) {
                uint32_t ah[8], bx[16];

#pragma unroll
                for (int f = 0; f < 2; f++) {
                    int row = warp_m * 32 + f * 16 + a_r;
                    ldsm4(&ah[4 * f],
                          sAh + (uint32_t)(row * LDT + ks + a_c) * 2);
                }
#pragma unroll
                for (int g = 0; g < 4; g++) {
                    int row = warp_n * 64 + g * 16 + b_r;
                    ldsm4(&bx[4 * g],
                          sBh + (uint32_t)(row * LDT + ks + b_c) * 2);
                }
                // hh
#pragma unroll
                for (int f = 0; f < 2; f++)
#pragma unroll
                    for (int j = 0; j < 8; j++)
                        mma_bf16(acc[f][j], &ah[4 * f], &bx[2 * j]);

                // lh: al x bh
                {
                    uint32_t al[8];
#pragma unroll
                    for (int f = 0; f < 2; f++) {
                        int row = warp_m * 32 + f * 16 + a_r;
                        ldsm4(&al[4 * f],
                              sAl + (uint32_t)(row * LDT + ks + a_c) * 2);
                    }
#pragma unroll
                    for (int f = 0; f < 2; f++)
#pragma unroll
                        for (int j = 0; j < 8; j++)
                            mma_bf16(acc[f][j], &al[4 * f], &bx[2 * j]);
                }
                // hl: ah x bl (overwrite bx)
#pragma unroll
                for (int g = 0; g < 4; g++) {
                    int row = warp_n * 64 + g * 16 + b_r;
                    ldsm4(&bx[4 * g],
                          sBl + (uint32_t)(row * LDT + ks + b_c) * 2);
                }
#pragma unroll
                for (int f = 0; f < 2; f++)
#pragma unroll
                    for (int j = 0; j < 8; j++)
                        mma_bf16(acc[f][j], &ah[4 * f], &bx[2 * j]);
            }
            __syncthreads();
        }
    }

    // ---- epilogue ----
#pragma unroll
    for (int f = 0; f < 2; f++) {
        int r0 = warp_m * 32 + f * 16 + (lane >> 2);
#pragma unroll
        for (int half = 0; half < 2; half++) {
            int gr = bm + r0 + half * 8;
            if (gr >= M) continue;
            float* crow = C + (size_t)gr * N;
            const float* arow = addend ? addend + (size_t)gr * N : nullptr;
#pragma unroll
            for (int j = 0; j < 8; j++) {
                int col = bn + warp_n * 64 + j * 8 + (lane & 3) * 2;
                float2 v;
                v.x = acc[f][j][half * 2 + 0];
                v.y = acc[f][j][half * 2 + 1];
                if (bias) {
                    float2 b = *(const float2*)(bias + col);
                    v.x += b.x; v.y += b.y;
                }
                if (arow) {
                    float2 a = *(const float2*)(arow + col);
                    v.x += a.x; v.y += a.y;
                }
                if (do_relu) {
                    v.x = fmaxf(v.x, 0.f);
                    v.y = fmaxf(v.y, 0.f);
                }
                *(float2*)(crow + col) = v;
            }
        }
    }
}

// ---------------------------------------------------------------------------
// Edge scatter-add, F=128:  agg[sidx[e]] += x[gidx[e]]  (red.global.add.v4)
// ---------------------------------------------------------------------------
__global__ void __launch_bounds__(256) scatter_add128_kernel(
    const float* __restrict__ x,
    const int* __restrict__ gidx,
    const int* __restrict__ sidx,
    float* __restrict__ agg, int E)
{
    long long idx = (long long)blockIdx.x * blockDim.x + threadIdx.x;
    if (idx >= (long long)E * 32) return;
    int e = (int)(idx >> 5);
    int c = (int)(idx & 31) * 4;

    int g = __ldg(gidx + e);
    int s = __ldg(sidx + e);
    float4 v = *(const float4*)(x + (size_t)g * 128 + c);
    float* p = agg + (size_t)s * 128 + c;
    asm volatile("red.global.add.v4.f32 [%0], {%1, %2, %3, %4};"
                 :: "l"(p), "f"(v.x), "f"(v.y), "f"(v.z), "f"(v.w)
                 : "memory");
}

// ---------------------------------------------------------------------------

extern "C" void kernel_launch(void* const* d_in, const int* in_sizes, int n_in,
                              void* d_out, int out_size)
{
    const float* x_user       = (const float*)d_in[0];
    const float* x_issue      = (const float*)d_in[1];
    const float* W_mlp        = (const float*)d_in[2];
    const float* b_mlp        = (const float*)d_in[3];
    const float* c1_ui_rel_W  = (const float*)d_in[4];
    const float* c1_ui_rel_b  = (const float*)d_in[5];
    const float* c1_ui_root_W = (const float*)d_in[6];
    const float* c1_iu_rel_W  = (const float*)d_in[7];
    const float* c1_iu_rel_b  = (const float*)d_in[8];
    const float* c1_iu_root_W = (const float*)d_in[9];
    const float* c2_ui_rel_W  = (const float*)d_in[10];
    const float* c2_ui_rel_b  = (const float*)d_in[11];
    const float* c2_ui_root_W = (const float*)d_in[12];
    const float* c2_iu_rel_W  = (const float*)d_in[13];
    const float* c2_iu_rel_b  = (const float*)d_in[14];
    const float* c2_iu_root_W = (const float*)d_in[15];
    const int*   src          = (const int*)d_in[16];
    const int*   dst          = (const int*)d_in[17];

    float* out       = (float*)d_out;
    float* out_issue = out;
    float* out_user  = out + (size_t)NI * DOUT;

    float* S = nullptr;
    cudaGetSymbolAddress((void**)&S, g_scratch);
    float* xi    = S + OFF_XI;
    float* agg_i = S + OFF_AGG_I;
    float* agg_u = S + OFF_AGG_U;
    float* h_i   = S + OFF_H_I;
    float* h_u   = S + OFF_H_U;
    float* y_u2  = S + OFF_Y_U2;
    float* y_i2  = S + OFF_Y_I2;

    // one-time creation of side stream + events (first call is the
    // non-captured correctness run; capture replays only record/wait edges)
    static cudaStream_t s2 = nullptr;
    static cudaEvent_t ev_ms, ev_g1, ev_g4, ev_g5, ev_s3;
    if (!s2) {
        cudaStreamCreateWithFlags(&s2, cudaStreamNonBlocking);
        cudaEventCreateWithFlags(&ev_ms, cudaEventDisableTiming);
        cudaEventCreateWithFlags(&ev_g1, cudaEventDisableTiming);
        cudaEventCreateWithFlags(&ev_g4, cudaEventDisableTiming);
        cudaEventCreateWithFlags(&ev_g5, cudaEventDisableTiming);
        cudaEventCreateWithFlags(&ev_s3, cudaEventDisableTiming);
    }

    dim3 blk(256);
    const int snb = (int)(((long long)NE * 32 + 255) / 256);
    const int gNI = (NI + 127) / 128;
    const int gNU = (NU + 127) / 128;

    // ---------------- stream 0 (default) : user-side chain ----------------
    // zero conv1 aggregation buffers (contiguous agg_i|agg_u)
    cudaMemsetAsync(agg_i, 0, ((size_t)NI + NU) * DIN * sizeof(float), 0);
    cudaEventRecord(ev_ms, 0);

    // G1: xi = x_issue @ W_mlp^T + b_mlp
    gemm_mma_kernel<<<dim3(gNI, 1), blk, 0, 0>>>(
        x_issue, W_mlp, b_mlp, nullptr, nullptr, nullptr,
        xi, NI, DIN, DIN, 0);
    cudaEventRecord(ev_g1, 0);

    // ---------------- stream s2 : issue-side chain -------------------------
    cudaStreamWaitEvent(s2, ev_ms, 0);
    // S1: agg_i += scatter(x_user)
    scatter_add128_kernel<<<snb, blk, 0, s2>>>(x_user, src, dst, agg_i, NE);
    cudaStreamWaitEvent(s2, ev_g1, 0);
    // G2: h_i = relu(agg_i@c1_ui_rel^T + b + xi@c1_ui_root^T)
    gemm_mma_kernel<<<dim3(gNI, 2), blk, 0, s2>>>(
        agg_i, c1_ui_rel_W, c1_ui_rel_b, xi, c1_ui_root_W, nullptr,
        h_i, NI, DHID, DIN, 1);
    // G5: y_i2 = h_i @ c2_iu_rel^T
    gemm_mma_kernel<<<dim3(gNI, 1), blk, 0, s2>>>(
        h_i, c2_iu_rel_W, nullptr, nullptr, nullptr, nullptr,
        y_i2, NI, DOUT, DHID, 0);
    cudaEventRecord(ev_g5, s2);
    // G6: out_issue = h_i@c2_ui_root^T + c2_ui_rel_b
    gemm_mma_kernel<<<dim3(gNI, 1), blk, 0, s2>>>(
        h_i, c2_ui_root_W, c2_ui_rel_b, nullptr, nullptr, nullptr,
        out_issue, NI, DOUT, DHID, 0);

    // ---------------- stream 0 continues -----------------------------------
    // S2: agg_u += scatter(xi)
    scatter_add128_kernel<<<snb, blk, 0, 0>>>(xi, dst, src, agg_u, NE);
    // G3: h_u = relu(agg_u@c1_iu_rel^T + b + x_user@c1_iu_root^T)
    gemm_mma_kernel<<<dim3(gNU, 2), blk, 0, 0>>>(
        agg_u, c1_iu_rel_W, c1_iu_rel_b, x_user, c1_iu_root_W, nullptr,
        h_u, NU, DHID, DIN, 1);
    // G4: y_u2 = h_u @ c2_ui_rel^T
    gemm_mma_kernel<<<dim3(gNU, 1), blk, 0, 0>>>(
        h_u, c2_ui_rel_W, nullptr, nullptr, nullptr, nullptr,
        y_u2, NU, DOUT, DHID, 0);
    cudaEventRecord(ev_g4, 0);
    // G7: out_user = h_u@c2_iu_root^T + c2_iu_rel_b
    gemm_mma_kernel<<<dim3(gNU, 1), blk, 0, 0>>>(
        h_u, c2_iu_root_W, c2_iu_rel_b, nullptr, nullptr, nullptr,
        out_user, NU, DOUT, DHID, 0);

    // S3 on s2: out_issue += scatter(y_u2)   (needs G4 + G6)
    cudaStreamWaitEvent(s2, ev_g4, 0);
    scatter_add128_kernel<<<snb, blk, 0, s2>>>(y_u2, src, dst, out_issue, NE);
    cudaEventRecord(ev_s3, s2);

    // S4 on stream 0: out_user += scatter(y_i2)   (needs G5 + G7)
    cudaStreamWaitEvent(0, ev_g5, 0);
    scatter_add128_kernel<<<snb, blk, 0, 0>>>(y_i2, dst, src, out_user, NE);

    // join side stream back into stream 0
    cudaStreamWaitEvent(0, ev_s3, 0);
}